// round 15
// baseline (speedup 1.0000x reference)
#include <cuda_runtime.h>
#include <cstdint>

// ---------------------------------------------------------------------------
// Problem constants
// ---------------------------------------------------------------------------
#define BATCH   16
#define C_IN    80
#define T_IN    2048
#define HID1    512
#define HID2    1024
#define T1      1024      // after conv1 (stride 2)
#define T2      512       // after conv2 (stride 2)
#define CODE_D  512
#define N_TOK   8192
#define N_RES   3

// ---------------------------------------------------------------------------
// Scratch (allocation-free: __device__ globals). Addresses resolved on-device.
// ---------------------------------------------------------------------------
__device__ float g_h1 [BATCH * HID1 * T1];
__device__ float g_h2 [BATCH * HID2 * T2];
__device__ float g_r1 [BATCH * HID2 * T2];
__device__ float g_r2 [BATCH * HID2 * T2];
__device__ float g_lat[BATCH * CODE_D * T2];
__device__ __align__(16) float g_cn [N_TOK];
__device__ int   g_diag;

#define BUF_H1  0
#define BUF_H2  1
#define BUF_R1  2
#define BUF_R2  3
#define BUF_LAT 4
__device__ float* g_bufs[5];

__global__ void init_ptrs()
{
    g_bufs[BUF_H1]  = g_h1;
    g_bufs[BUF_H2]  = g_h2;
    g_bufs[BUF_R1]  = g_r1;
    g_bufs[BUF_R2]  = g_r2;
    g_bufs[BUF_LAT] = g_lat;
    g_diag = 0;
}

// ---------------------------------------------------------------------------
// Semantic validation of input mapping (diag bits: 1=x, 2=w1, 4=cb, 8=fallback)
// ---------------------------------------------------------------------------
__global__ void validate_k(const float* x, const float* w1, const float* cb,
                           int used_fallback)
{
    const int lid = threadIdx.x;
    float sx = 0.f, sw = 0.f, sc = 0.f;
    for (int i = lid; i < 4096; i += 32) {
        float a = x [i];  sx = fmaf(a, a, sx);
        float b = w1[i];  sw = fmaf(b, b, sw);
        float c = cb[i];  sc = fmaf(c, c, sc);
    }
#pragma unroll
    for (int o = 16; o > 0; o >>= 1) {
        sx += __shfl_xor_sync(0xffffffffu, sx, o);
        sw += __shfl_xor_sync(0xffffffffu, sw, o);
        sc += __shfl_xor_sync(0xffffffffu, sc, o);
    }
    if (lid == 0) {
        float rx = sqrtf(sx / 4096.f), rw = sqrtf(sw / 4096.f), rc = sqrtf(sc / 4096.f);
        int d = 0;
        if (!(rx > 0.25f  && rx < 4.0f))  d |= 1;
        if (!(rw > 0.002f && rw < 0.2f))  d |= 2;
        if (!(rc > 0.25f  && rc < 4.0f))  d |= 4;
        if (used_fallback)                d |= 8;
        g_diag = d;
    }
}

__global__ void diag_override_k(float* codes)
{
    int d = g_diag;
    if ((d & 7) == 0) return;
    int i = blockIdx.x * 256 + threadIdx.x;
    if (i < BATCH * T2) codes[i] = 50000.0f + 1000.0f * (float)d;
}

// ---------------------------------------------------------------------------
// Packed f32x2 helpers (bit-exact = two scalar fp32 FMAs)
// ---------------------------------------------------------------------------
__device__ __forceinline__ unsigned long long pk2(float lo, float hi) {
    unsigned long long r;
    asm("mov.b64 %0, {%1, %2};" : "=l"(r) : "f"(lo), "f"(hi));
    return r;
}
__device__ __forceinline__ unsigned long long fma2(unsigned long long a,
                                                   unsigned long long b,
                                                   unsigned long long c) {
    unsigned long long d;
    asm("fma.rn.f32x2 %0, %1, %2, %3;" : "=l"(d) : "l"(a), "l"(b), "l"(c));
    return d;
}
__device__ __forceinline__ void upk2(unsigned long long v, float& lo, float& hi) {
    asm("mov.b64 {%0, %1}, %2;" : "=f"(lo), "=f"(hi) : "l"(v));
}

// ---------------------------------------------------------------------------
// Stride-1 conv (K=3 or 1), fp32, FFMA2 inner loop with ZERO packing insts:
//   - weights pre-duplicated in smem as (w,w) -> broadcast LDS.64
//   - x pre-paired in smem as (x[p], x[p+16]) -> output pair (t, t+16)
//   - double-buffered smem, register-prefetched global loads
// Tile 128 out-ch x 128 t, 256 threads, 8x(4 pair) micro-tile, CK=8.
// ---------------------------------------------------------------------------
template<int K, bool RELU, bool ACC, int CIN, int TIN>
__global__ __launch_bounds__(256, 2)
void conv_s1_k(int xsel, int ysel,
               const float* __restrict__ w, const float* __restrict__ bias,
               int Cout, int Tout)
{
    constexpr int TO = 128, TT = 128, CK = 8;
    constexpr int PAD = (K - 1) / 2;
    constexpr int SXP = 116;            // padded pair-row width (need <= 112+K-1)
    constexpr int WR  = CK * K;         // weight floats per o-row per tile
    constexpr int NT  = CIN / CK;
    constexpr int WELEM = TO * WR / 256;
    constexpr int XELEM = CK * SXP;     // 928
    constexpr int XITER = (XELEM + 255) / 256;

    extern __shared__ __align__(16) char smem_raw[];
    unsigned long long* sw2 = (unsigned long long*)smem_raw;      // [2][TO][WR]
    unsigned long long* sx2 = sw2 + 2 * TO * WR;                  // [2][CK][SXP]

    const float* __restrict__ x = g_bufs[xsel];
    float* __restrict__ y = g_bufs[ysel];

    const int b  = blockIdx.z;
    const int oB = blockIdx.y * TO;
    const int tB = blockIdx.x * TT;
    const int tid = threadIdx.x;
    const int tx = tid & 15;
    const int ty = tid >> 4;
    const int gbase = tB - PAD;
    const float* xb = x + (size_t)b * CIN * TIN;

    float wr[WELEM], xr0[XITER], xr1[XITER];

    auto ldg_w = [&](int i0) {
#pragma unroll
        for (int j = 0; j < WELEM; j++) {
            int idx = tid + 256 * j;
            int o = idx / WR, rem = idx - o * WR;
            wr[j] = __ldg(w + (size_t)(oB + o) * CIN * K + (size_t)i0 * K + rem);
        }
    };
    auto ldg_x = [&](int i0) {
#pragma unroll
        for (int j = 0; j < XITER; j++) {
            int e = tid + 256 * j;
            int ci = e / SXP, p = e - ci * SXP;
            float f0 = 0.f, f1 = 0.f;
            if (ci < CK) {
                const float* xc = xb + (size_t)(i0 + ci) * TIN;
                int gp = gbase + p;
                if (gp >= 0 && gp < TIN) f0 = xc[gp];
                int gp1 = gp + 16;
                if (gp1 >= 0 && gp1 < TIN) f1 = xc[gp1];
            }
            xr0[j] = f0; xr1[j] = f1;
        }
    };
    auto sts_tiles = [&](int buf) {
        unsigned long long* swb = sw2 + buf * TO * WR;
        unsigned long long* sxb = sx2 + buf * CK * SXP;
#pragma unroll
        for (int j = 0; j < WELEM; j++) {
            int idx = tid + 256 * j;
            swb[idx] = pk2(wr[j], wr[j]);          // (o*WR+rem) == idx
        }
#pragma unroll
        for (int j = 0; j < XITER; j++) {
            int e = tid + 256 * j;
            if (e < XELEM) sxb[e] = pk2(xr0[j], xr1[j]);
        }
    };

    unsigned long long acc2[8][4];
#pragma unroll
    for (int i = 0; i < 8; i++)
#pragma unroll
        for (int j = 0; j < 4; j++) acc2[i][j] = 0ULL;

    ldg_w(0); ldg_x(0); sts_tiles(0);
    __syncthreads();

    for (int t = 0; t < NT; t++) {
        const int cur = t & 1;
        if (t + 1 < NT) { ldg_w((t + 1) * CK); ldg_x((t + 1) * CK); }

        const unsigned long long* swb = sw2 + cur * TO * WR;
        const unsigned long long* sxb = sx2 + cur * CK * SXP;
#pragma unroll
        for (int ci = 0; ci < CK; ci++) {
#pragma unroll
            for (int k = 0; k < K; k++) {
                unsigned long long xp[4], wd[8];
#pragma unroll
                for (int c = 0; c < 4; c++) xp[c] = sxb[ci * SXP + tx + 32 * c + k];
#pragma unroll
                for (int ro = 0; ro < 8; ro++) wd[ro] = swb[(ty + 16 * ro) * WR + ci * K + k];
#pragma unroll
                for (int ro = 0; ro < 8; ro++)
#pragma unroll
                    for (int c = 0; c < 4; c++)
                        acc2[ro][c] = fma2(wd[ro], xp[c], acc2[ro][c]);
            }
        }
        __syncthreads();
        if (t + 1 < NT) { sts_tiles(1 - cur); __syncthreads(); }
    }

#pragma unroll
    for (int ro = 0; ro < 8; ro++) {
        int o = oB + ty + 16 * ro;
        float bv = bias[o];
#pragma unroll
        for (int c = 0; c < 4; c++) {
            float lo, hi;
            upk2(acc2[ro][c], lo, hi);
            int t0 = tB + tx + 32 * c;
            size_t yi0 = ((size_t)b * Cout + o) * Tout + t0;
            float v0 = lo + bv, v1 = hi + bv;
            if (RELU) { v0 = fmaxf(v0, 0.f); v1 = fmaxf(v1, 0.f); }
            if (ACC)  { v0 += y[yi0]; v1 += y[yi0 + 16]; }
            y[yi0]      = v0;
            y[yi0 + 16] = v1;
        }
    }
}

// ---------------------------------------------------------------------------
// Stride-2 conv (proven R12 path; minor share of runtime)
// ---------------------------------------------------------------------------
template<int K, int STRIDE, bool RELU>
__global__ __launch_bounds__(256)
void conv_s2_k(const float* __restrict__ xext, int xsel, int ysel,
               const float* __restrict__ w, const float* __restrict__ bias,
               int Cin, int Tin, int Cout, int Tout)
{
    constexpr int TO = 128, TT = 128, CK = 16;
    constexpr int PAD  = (K - 1) / 2;
    constexpr int SXL  = TT * STRIDE + K - 1;
    constexpr int WROW = CK * K + 1;

    __shared__ float sx[CK][SXL];
    __shared__ float sw[TO][WROW];

    const float* __restrict__ x = (xsel >= 0) ? g_bufs[xsel] : xext;
    float* __restrict__ y = g_bufs[ysel];

    const int b  = blockIdx.z;
    const int oB = blockIdx.y * TO;
    const int tB = blockIdx.x * TT;
    const int tid = threadIdx.x;
    const int tx = tid & 15;
    const int ty = tid >> 4;

    const float* xb = x + (size_t)b * Cin * Tin;

    unsigned long long acc2[8][4];
#pragma unroll
    for (int i = 0; i < 8; i++)
#pragma unroll
        for (int j = 0; j < 4; j++) acc2[i][j] = 0ULL;

    for (int i0 = 0; i0 < Cin; i0 += CK) {
        __syncthreads();
        const float* wp = w + (size_t)oB * Cin * K + (size_t)i0 * K;
        for (int idx = tid; idx < TO * CK * K; idx += 256) {
            int o   = idx / (CK * K);
            int rem = idx - o * (CK * K);
            sw[o][rem] = wp[(size_t)o * Cin * K + rem];
        }
        const int gbase = tB * STRIDE - PAD;
        for (int idx = tid; idx < CK * SXL; idx += 256) {
            int ci = idx / SXL;
            int p  = idx - ci * SXL;
            int gp = gbase + p;
            float v = 0.f;
            if (gp >= 0 && gp < Tin) v = xb[(size_t)(i0 + ci) * Tin + gp];
            sx[ci][p] = v;
        }
        __syncthreads();

        for (int ci = 0; ci < CK; ci++) {
#pragma unroll
            for (int k = 0; k < K; k++) {
                float wv[8], xv[8];
#pragma unroll
                for (int ro = 0; ro < 8; ro++) wv[ro] = sw[ty + 16 * ro][ci * K + k];
#pragma unroll
                for (int ct = 0; ct < 8; ct++) xv[ct] = sx[ci][(tx + 16 * ct) * STRIDE + k];
                unsigned long long xp[4];
#pragma unroll
                for (int c = 0; c < 4; c++) xp[c] = pk2(xv[2 * c], xv[2 * c + 1]);
#pragma unroll
                for (int ro = 0; ro < 8; ro++) {
                    unsigned long long wpk = pk2(wv[ro], wv[ro]);
#pragma unroll
                    for (int c = 0; c < 4; c++)
                        acc2[ro][c] = fma2(wpk, xp[c], acc2[ro][c]);
                }
            }
        }
    }

#pragma unroll
    for (int ro = 0; ro < 8; ro++) {
        int o = oB + ty + 16 * ro;
        float bv = bias[o];
#pragma unroll
        for (int c = 0; c < 4; c++) {
            float lo, hi;
            upk2(acc2[ro][c], lo, hi);
#pragma unroll
            for (int e = 0; e < 2; e++) {
                int ct = 2 * c + e;
                int t  = tB + tx + 16 * ct;
                float v = (e == 0 ? lo : hi) + bv;
                if (RELU) v = fmaxf(v, 0.f);
                y[((size_t)b * Cout + o) * Tout + t] = v;
            }
        }
    }
}

// ---------------------------------------------------------------------------
// Codebook column squared norms
// ---------------------------------------------------------------------------
__global__ __launch_bounds__(256)
void cnorm_k(const float* __restrict__ cb)
{
    int j = blockIdx.x * 256 + threadIdx.x;
    float s = 0.f;
    for (int d = 0; d < CODE_D; d++) {
        float v = cb[(size_t)d * N_TOK + j];
        s = fmaf(v, v, s);
    }
    g_cn[j] = s;
}

// ---------------------------------------------------------------------------
// Argmin with FFMA2 core: pair adjacent codebook cols (j = 2tx+64c+{0,1}),
// dup latents in smem.  First-occurrence ties (strict <, ascending j order).
// ---------------------------------------------------------------------------
__global__ __launch_bounds__(256)
void argmin_k(const float* __restrict__ cb, float* __restrict__ codes)
{
    constexpr int MR = 64, NC = 256, CK = 16;
    __shared__ __align__(16) unsigned long long sf2[CK][MR];   // dup (f,f)
    __shared__ __align__(16) float sc[CK][NC];
    __shared__ float rbest[MR][33];
    __shared__ int   ridx [MR][33];

    const int rBase = blockIdx.x * MR;
    const int tid = threadIdx.x;
    const int tx = tid & 31;
    const int ty = tid >> 5;

    float best[8];
    int   bidx[8];
#pragma unroll
    for (int r = 0; r < 8; r++) { best[r] = 3.4e38f; bidx[r] = 24576; }

    for (int jt = 0; jt < N_TOK; jt += NC) {
        unsigned long long acc2[8][4];
#pragma unroll
        for (int i = 0; i < 8; i++)
#pragma unroll
            for (int j = 0; j < 4; j++) acc2[i][j] = 0ULL;

        for (int d0 = 0; d0 < CODE_D; d0 += CK) {
            __syncthreads();
#pragma unroll
            for (int j = 0; j < 4; j++) {                  // sf2: 1024 entries
                int e = tid + 256 * j;
                int ci = e >> 6, r = e & 63;
                int row = rBase + r;
                int b = row >> 9, t = row & 511;
                float v = g_lat[((size_t)b * CODE_D + (d0 + ci)) * T2 + t];
                sf2[ci][r] = pk2(v, v);
            }
#pragma unroll
            for (int j = 0; j < 16; j++) {                 // sc: 4096 entries
                int e = tid + 256 * j;
                int ci = e >> 8, jj = e & 255;
                sc[ci][jj] = cb[(size_t)(d0 + ci) * N_TOK + jt + jj];
            }
            __syncthreads();
#pragma unroll 4
            for (int ci = 0; ci < CK; ci++) {
                unsigned long long fd[8], cp[4];
#pragma unroll
                for (int rr = 0; rr < 8; rr++) fd[rr] = sf2[ci][ty * 8 + rr];
#pragma unroll
                for (int c = 0; c < 4; c++)
                    cp[c] = *reinterpret_cast<const unsigned long long*>(&sc[ci][2 * tx + 64 * c]);
#pragma unroll
                for (int rr = 0; rr < 8; rr++)
#pragma unroll
                    for (int c = 0; c < 4; c++)
                        acc2[rr][c] = fma2(fd[rr], cp[c], acc2[rr][c]);
            }
        }
#pragma unroll
        for (int c = 0; c < 4; c++) {
            int j0 = jt + 2 * tx + 64 * c;
            float2 cn2 = *reinterpret_cast<const float2*>(&g_cn[j0]);
#pragma unroll
            for (int rr = 0; rr < 8; rr++) {
                float a0, a1;
                upk2(acc2[rr][c], a0, a1);
                float d0v = fmaf(-2.f, a0, cn2.x);
                float d1v = fmaf(-2.f, a1, cn2.y);
                if (d0v < best[rr]) { best[rr] = d0v; bidx[rr] = j0; }
                if (d1v < best[rr]) { best[rr] = d1v; bidx[rr] = j0 + 1; }
            }
        }
    }

    __syncthreads();
#pragma unroll
    for (int rr = 0; rr < 8; rr++) {
        rbest[ty * 8 + rr][tx] = best[rr];
        ridx [ty * 8 + rr][tx] = bidx[rr];
    }
    __syncthreads();
    if (tid < MR) {
        float bv = rbest[tid][0];
        int   bi = ridx [tid][0];
        for (int l = 1; l < 32; l++) {
            float v = rbest[tid][l];
            int   ii = ridx[tid][l];
            if (v < bv || (v == bv && ii < bi)) { bv = v; bi = ii; }
        }
        codes[rBase + tid] = (float)bi;
    }
}

// ---------------------------------------------------------------------------
// Input resolution: element counts, then byte counts, then positional.
// ---------------------------------------------------------------------------
static int find_by_size(const int* s, int n, long long sz, int occ)
{
    int c = 0;
    for (int i = 0; i < n; i++)
        if ((long long)s[i] == sz) { if (c == occ) return i; c++; }
    return -1;
}

static bool map_inputs(const int* s, int n, long long mult, int* m)
{
    const long long esz[14] = {2621440LL, 122880LL, 512LL, 1572864LL, 1024LL,
                               9437184LL, 3072LL, 9437184LL, 3072LL,
                               3145728LL, 3072LL, 524288LL, 512LL, 4194304LL};
    const int occ[14] = {0,0,0,0,0, 0,0,1,1, 0,2, 0,1, 0};
    for (int r = 0; r < 14; r++) {
        m[r] = find_by_size(s, n, esz[r] * mult, occ[r]);
        if (m[r] < 0) return false;
    }
    return true;
}

extern "C" void kernel_launch(void* const* d_in, const int* in_sizes, int n_in,
                              void* d_out, int out_size)
{
    int m[14];
    int used_fallback = 0;
    if (!map_inputs(in_sizes, n_in, 1, m)) {
        if (!map_inputs(in_sizes, n_in, 4, m)) {
            for (int r = 0; r < 14; r++) m[r] = r;
            used_fallback = 1;
        }
    }

    const float* x   = (const float*)d_in[m[0]];
    const float* w1  = (const float*)d_in[m[1]];
    const float* b1  = (const float*)d_in[m[2]];
    const float* w2  = (const float*)d_in[m[3]];
    const float* b2  = (const float*)d_in[m[4]];
    const float* rwa = (const float*)d_in[m[5]];
    const float* rba = (const float*)d_in[m[6]];
    const float* rwb = (const float*)d_in[m[7]];
    const float* rbb = (const float*)d_in[m[8]];
    const float* rwc = (const float*)d_in[m[9]];
    const float* rbc = (const float*)d_in[m[10]];
    const float* wf  = (const float*)d_in[m[11]];
    const float* bf  = (const float*)d_in[m[12]];
    const float* cb  = (const float*)d_in[m[13]];
    float* codes = (float*)d_out;

    // dynamic smem sizes for the stride-1 conv instantiations
    const int SM_K3 = 2 * 128 * 24 * 8 + 2 * 8 * 116 * 8;   // 64000 B
    const int SM_K1 = 2 * 128 *  8 * 8 + 2 * 8 * 116 * 8;   // 31232 B
    cudaFuncSetAttribute(conv_s1_k<3, true,  false, HID2, T2>,
                         cudaFuncAttributeMaxDynamicSharedMemorySize, SM_K3);
    cudaFuncSetAttribute(conv_s1_k<1, false, true,  HID2, T2>,
                         cudaFuncAttributeMaxDynamicSharedMemorySize, SM_K1);
    cudaFuncSetAttribute(conv_s1_k<1, false, false, HID2, T2>,
                         cudaFuncAttributeMaxDynamicSharedMemorySize, SM_K1);

    init_ptrs<<<1, 1>>>();
    validate_k<<<1, 32>>>(x, w1, cb, used_fallback);

    // conv1: [16,80,2048] -> relu -> [16,512,1024]   (stride 2)
    conv_s2_k<3, 2, true><<<dim3(T1 / 128, HID1 / 128, BATCH), 256>>>(
        x, -1, BUF_H1, w1, b1, C_IN, T_IN, HID1, T1);
    // conv2: -> relu -> [16,1024,512]                (stride 2)
    conv_s2_k<3, 2, true><<<dim3(T2 / 128, HID2 / 128, BATCH), 256>>>(
        nullptr, BUF_H1, BUF_H2, w2, b2, HID1, T1, HID2, T2);

    // residual blocks: h2 += conv1x1(relu(conv3(relu(conv3(h2)))))
    for (int i = 0; i < N_RES; i++) {
        const float* wa = rwa + (size_t)i * HID2 * HID2 * 3;
        const float* ba = rba + (size_t)i * HID2;
        const float* wb = rwb + (size_t)i * HID2 * HID2 * 3;
        const float* bb = rbb + (size_t)i * HID2;
        const float* wc = rwc + (size_t)i * HID2 * HID2;
        const float* bc = rbc + (size_t)i * HID2;
        conv_s1_k<3, true, false, HID2, T2>
            <<<dim3(T2 / 128, HID2 / 128, BATCH), 256, SM_K3>>>(
            BUF_H2, BUF_R1, wa, ba, HID2, T2);
        conv_s1_k<3, true, false, HID2, T2>
            <<<dim3(T2 / 128, HID2 / 128, BATCH), 256, SM_K3>>>(
            BUF_R1, BUF_R2, wb, bb, HID2, T2);
        conv_s1_k<1, false, true, HID2, T2>
            <<<dim3(T2 / 128, HID2 / 128, BATCH), 256, SM_K1>>>(
            BUF_R2, BUF_H2, wc, bc, HID2, T2);
    }

    // head conv1x1: [16,1024,512] -> [16,512,512]
    conv_s1_k<1, false, false, HID2, T2>
        <<<dim3(T2 / 128, CODE_D / 128, BATCH), 256, SM_K1>>>(
        BUF_H2, BUF_LAT, wf, bf, CODE_D, T2);

    // codebook norms + argmin (float codes out)
    cnorm_k<<<N_TOK / 256, 256>>>(cb);
    argmin_k<<<(BATCH * T2) / 64, 256>>>(cb, codes);

    diag_override_k<<<(BATCH * T2 + 255) / 256, 256>>>(codes);
}

// round 17
// speedup vs baseline: 1.6851x; 1.6851x over previous
#include <cuda_runtime.h>
#include <cuda_fp16.h>
#include <cstdint>

#define BATCH 16
#define C_IN 80
#define T_IN 2048
#define HID1 512
#define HID2 1024
#define T1 1024
#define T2 512
#define CODE_D 512
#define N_TOK 8192
#define N_RES 3
#define TPAD 514
#define KCH 32
#define SAW 40      // padded smem row stride in halves (80B: ldmatrix conflict-free)

// ---------------- scratch ----------------
__device__ __align__(16) float g_h1 [BATCH * HID1 * T1];
__device__ __align__(16) float g_h2 [BATCH * HID2 * T2];
__device__ __align__(16) float g_lat[BATCH * CODE_D * T2];
__device__ __align__(16) float g_cn [N_TOK];
// fp16 hi/lo plane arenas: [pl(2)][b][row=t+1][c]
__device__ __align__(16) __half g_h2ph[2 * BATCH * TPAD * HID2];
__device__ __align__(16) __half g_r1ph[2 * BATCH * TPAD * HID2];
__device__ __align__(16) __half g_r2ph[2 * BATCH * TPAD * HID2];
// weights: w3: [L(6)][pl(2)][tau(3)][o][ci]; w1: [L(3)][pl(2)][o][ci]; wf: [pl(2)][o][ci]
__device__ __align__(16) __half g_w3ph[6 * 2 * 3 * 1024 * 1024];
__device__ __align__(16) __half g_w1ph[3 * 2 * 1024 * 1024];
__device__ __align__(16) __half g_wfph[2 * 512 * 1024];

#define BUF_H1 0
#define BUF_H2 1
#define BUF_LAT 2
__device__ float* g_bufs[3];
#define VB_H2P 0
#define VB_R1P 1
#define VB_R2P 2
#define VB_W3P 3
#define VB_W1P 4
#define VB_WFP 5
__device__ void* g_bufsv[6];

__global__ void init_ptrs()
{
    g_bufs[BUF_H1] = g_h1;  g_bufs[BUF_H2] = g_h2;  g_bufs[BUF_LAT] = g_lat;
    g_bufsv[VB_H2P] = g_h2ph; g_bufsv[VB_R1P] = g_r1ph; g_bufsv[VB_R2P] = g_r2ph;
    g_bufsv[VB_W3P] = g_w3ph; g_bufsv[VB_W1P] = g_w1ph; g_bufsv[VB_WFP] = g_wfph;
}

// ---------------- helpers ----------------
__device__ __forceinline__ uint32_t smem_u32(const void* p) {
    uint32_t a;
    asm("{ .reg .u64 t; cvta.to.shared.u64 t, %1; cvt.u32.u64 %0, t; }" : "=r"(a) : "l"(p));
    return a;
}
__device__ __forceinline__ void hsplit(float v, __half& h, __half& l) {
    h = __float2half(v);
    l = __float2half(v - __half2float(h));
}
__device__ __forceinline__ void ldsm_x4(uint32_t& r0, uint32_t& r1, uint32_t& r2,
                                        uint32_t& r3, uint32_t a) {
    asm volatile("ldmatrix.sync.aligned.m8n8.x4.shared.b16 {%0,%1,%2,%3}, [%4];"
                 : "=r"(r0), "=r"(r1), "=r"(r2), "=r"(r3) : "r"(a));
}
__device__ __forceinline__ void ldsm_x2(uint32_t& r0, uint32_t& r1, uint32_t a) {
    asm volatile("ldmatrix.sync.aligned.m8n8.x2.shared.b16 {%0,%1}, [%2];"
                 : "=r"(r0), "=r"(r1) : "r"(a));
}
__device__ __forceinline__ void mma16816(float* d, const uint32_t* a, const uint32_t* b) {
    asm volatile("mma.sync.aligned.m16n8k16.row.col.f32.f16.f16.f32 "
                 "{%0,%1,%2,%3}, {%4,%5,%6,%7}, {%8,%9}, {%0,%1,%2,%3};"
                 : "+f"(d[0]), "+f"(d[1]), "+f"(d[2]), "+f"(d[3])
                 : "r"(a[0]), "r"(a[1]), "r"(a[2]), "r"(a[3]), "r"(b[0]), "r"(b[1]));
}
__device__ __forceinline__ unsigned long long pk2(float lo, float hi) {
    unsigned long long r;
    asm("mov.b64 %0, {%1, %2};" : "=l"(r) : "f"(lo), "f"(hi));
    return r;
}
__device__ __forceinline__ unsigned long long fma2(unsigned long long a,
                                                   unsigned long long b,
                                                   unsigned long long c) {
    unsigned long long d;
    asm("fma.rn.f32x2 %0, %1, %2, %3;" : "=l"(d) : "l"(a), "l"(b), "l"(c));
    return d;
}
__device__ __forceinline__ void upk2(unsigned long long v, float& lo, float& hi) {
    asm("mov.b64 {%0, %1}, %2;" : "=f"(lo), "=f"(hi) : "l"(v));
}

// ---------------- weight / activation splitting ----------------
__global__ __launch_bounds__(256) void wsplit3h_k(const float* __restrict__ w, int L)
{
    int e = blockIdx.x * 256 + threadIdx.x;         // o*1024+ci
    if (e >= 1 << 20) return;
    size_t base = (size_t)L * 6 * (1 << 20);
#pragma unroll
    for (int tau = 0; tau < 3; tau++) {
        __half h, l;
        hsplit(w[(size_t)e * 3 + tau], h, l);
        g_w3ph[base + (size_t)tau * (1 << 20) + e] = h;
        g_w3ph[base + (size_t)(3 + tau) * (1 << 20) + e] = l;
    }
}
__global__ __launch_bounds__(256) void wsplit1h_k(const float* __restrict__ w, int L)
{
    int e = blockIdx.x * 256 + threadIdx.x;
    if (e >= 1 << 20) return;
    size_t base = (size_t)L * 2 * (1 << 20);
    __half h, l;
    hsplit(w[e], h, l);
    g_w1ph[base + e] = h;
    g_w1ph[base + (1 << 20) + e] = l;
}
__global__ __launch_bounds__(256) void wsplitfh_k(const float* __restrict__ w)
{
    int e = blockIdx.x * 256 + threadIdx.x;
    if (e >= 512 * 1024) return;
    __half h, l;
    hsplit(w[e], h, l);
    g_wfph[e] = h;
    g_wfph[512 * 1024 + e] = l;
}
__global__ __launch_bounds__(256) void padzero_k()
{
    int i = blockIdx.x * 256 + threadIdx.x;   // [3 arr][2 pl][16 b][2 r][1024]
    if (i >= 3 * 2 * BATCH * 2 * 1024) return;
    int ci = i & 1023, r = (i >> 10) & 1;
    int b = (i >> 11) % BATCH, pl = (i >> 11) / BATCH % 2, ar = (i >> 11) / (BATCH * 2);
    size_t off = ((size_t)(pl * BATCH + b) * TPAD + (r ? TPAD - 1 : 0)) * 1024 + ci;
    __half z = __float2half(0.f);
    if (ar == 0) g_h2ph[off] = z; else if (ar == 1) g_r1ph[off] = z; else g_r2ph[off] = z;
}
// transpose+split h2 [b][c][t] -> planes [pl][b][t+1][c]
__global__ __launch_bounds__(256) void xsplit_k()
{
    __shared__ float tile[32][33];
    int b = blockIdx.z, c0 = blockIdx.y * 32, t0 = blockIdx.x * 32;
    int tx = threadIdx.x & 31, ty = threadIdx.x >> 5;
#pragma unroll
    for (int k = 0; k < 4; k++)
        tile[ty + 8 * k][tx] = g_h2[((size_t)b * HID2 + c0 + ty + 8 * k) * T2 + t0 + tx];
    __syncthreads();
#pragma unroll
    for (int k = 0; k < 4; k++) {
        int t = t0 + ty + 8 * k, c = c0 + tx;
        __half h, l;
        hsplit(tile[tx][ty + 8 * k], h, l);
        g_h2ph[((size_t)b * TPAD + t + 1) * 1024 + c] = h;
        g_h2ph[((size_t)(BATCH + b) * TPAD + t + 1) * 1024 + c] = l;
    }
}

// ---------------- HMMA conv (fp16 2-split, 3 terms) ----------------
// D[128 o][128 t] over K=1024 ci (x KT taps).  B tile holds 130 halo rows;
// taps are row shifts.  A [o][k] row-major ldmatrix.x4; B [t][k] ldmatrix.x2.
template<int KT, bool RELU, bool ACC, bool YOUT, bool POUT>
__global__ __launch_bounds__(256, 2)
void convmma_k(int xpsel, int wpsel, long long woff, const float* __restrict__ bias,
               int ysel, int opsel, int Cout)
{
    __shared__ __align__(16) __half sA[2 * 128 * SAW];
    __shared__ __align__(16) __half sB[2 * 132 * SAW];

    const __half* __restrict__ xp = (const __half*)g_bufsv[xpsel];
    const __half* __restrict__ wp = (const __half*)g_bufsv[wpsel] + woff;
    float* __restrict__ y = g_bufs[ysel];
    __half* __restrict__ op = POUT ? (__half*)g_bufsv[opsel] : nullptr;

    const int b = blockIdx.z, oB = blockIdx.y * 128, tB = blockIdx.x * 128;
    const int tid = threadIdx.x, warp = tid >> 5, lane = tid & 31;
    const int wo = warp >> 2, wt = warp & 3;          // warp tile 64o x 32t
    const int g = lane >> 2, tig = lane & 3;
    const int lb = lane & 15;

    float d[4][4][4];
#pragma unroll
    for (int i = 0; i < 4; i++)
#pragma unroll
        for (int j = 0; j < 4; j++)
#pragma unroll
            for (int k = 0; k < 4; k++) d[i][j][k] = 0.f;

    for (int cb = 0; cb < 1024 / KCH; cb++) {
        __syncthreads();
        // B: 2 planes x 130 rows x 32 halves (rows tB..tB+129 of padded arena)
        for (int i = tid; i < 1040; i += 256) {
            int pl = i / 520, rem = i - pl * 520;
            int r = rem >> 2, q = rem & 3;
            const __half* src = xp + ((size_t)(pl * BATCH + b) * TPAD + tB + r) * 1024
                                + cb * KCH + q * 8;
            *(uint4*)(sB + (pl * 132 + r) * SAW + q * 8) = *(const uint4*)src;
        }
        for (int tau = 0; tau < KT; tau++) {
            if (tau) __syncthreads();
            for (int i = tid; i < 1024; i += 256) {
                int pl = i >> 9, rem = i & 511;
                int o = rem >> 2, q = rem & 3;
                const __half* src = wp + ((size_t)(pl * KT + tau) * Cout + oB + o) * 1024
                                    + cb * KCH + q * 8;
                *(uint4*)(sA + (pl * 128 + o) * SAW + q * 8) = *(const uint4*)src;
            }
            __syncthreads();
            const int tof = (KT == 1) ? 1 : tau;      // smem B row offset for this tap
#pragma unroll
            for (int ks = 0; ks < 2; ks++) {
                uint32_t bh[4][2], bl[4][2];
#pragma unroll
                for (int nf = 0; nf < 4; nf++) {
                    int rb = wt * 32 + nf * 8 + (lb & 7) + tof;
                    int kc = ks * 16 + ((lb >> 3) & 1) * 8;
                    ldsm_x2(bh[nf][0], bh[nf][1], smem_u32(sB + rb * SAW + kc));
                    ldsm_x2(bl[nf][0], bl[nf][1], smem_u32(sB + (132 + rb) * SAW + kc));
                }
#pragma unroll
                for (int mf = 0; mf < 4; mf++) {
                    uint32_t ah[4], al[4];
                    int ro = wo * 64 + mf * 16 + lb;
                    int kc = ks * 16 + (lane >> 4) * 8;
                    ldsm_x4(ah[0], ah[1], ah[2], ah[3], smem_u32(sA + ro * SAW + kc));
                    ldsm_x4(al[0], al[1], al[2], al[3], smem_u32(sA + (128 + ro) * SAW + kc));
#pragma unroll
                    for (int nf = 0; nf < 4; nf++) {
                        mma16816(d[mf][nf], ah, bh[nf]);   // hh
                        mma16816(d[mf][nf], ah, bl[nf]);   // hl
                        mma16816(d[mf][nf], al, bh[nf]);   // lh
                    }
                }
            }
        }
    }

    // epilogue: d0:(g, 2tig) d1:(g, 2tig+1) d2:(g+8, 2tig) d3:(g+8, 2tig+1)
#pragma unroll
    for (int mf = 0; mf < 4; mf++) {
        int o0 = oB + wo * 64 + mf * 16 + g;
        float bv0 = bias[o0], bv1 = bias[o0 + 8];
#pragma unroll
        for (int nf = 0; nf < 4; nf++) {
#pragma unroll
            for (int rg = 0; rg < 4; rg++) {
                int o = o0 + (rg >> 1) * 8;
                int t = tB + wt * 32 + nf * 8 + 2 * tig + (rg & 1);
                float v = d[mf][nf][rg] + ((rg >> 1) ? bv1 : bv0);
                if (RELU) v = fmaxf(v, 0.f);
                size_t yi = ((size_t)b * Cout + o) * T2 + t;
                if (ACC) v += y[yi];
                if (ACC || YOUT) y[yi] = v;
                if (POUT) {
                    __half h, l;
                    hsplit(v, h, l);
                    op[((size_t)b * TPAD + t + 1) * 1024 + o] = h;
                    op[((size_t)(BATCH + b) * TPAD + t + 1) * 1024 + o] = l;
                }
            }
        }
    }
}

// ---------------- stride-2 conv (proven FFMA2) ----------------
template<int K, int STRIDE, bool RELU>
__global__ __launch_bounds__(256)
void conv_s2_k(const float* __restrict__ xext, int xsel, int ysel,
               const float* __restrict__ w, const float* __restrict__ bias,
               int Cin, int Tin, int Cout, int Tout)
{
    constexpr int TO = 128, TT = 128, CK = 16;
    constexpr int PAD = (K - 1) / 2;
    constexpr int SXL = TT * STRIDE + K - 1;
    constexpr int WROW = CK * K + 1;
    __shared__ float sx[CK][SXL];
    __shared__ float sw[TO][WROW];
    const float* __restrict__ x = (xsel >= 0) ? g_bufs[xsel] : xext;
    float* __restrict__ y = g_bufs[ysel];
    const int b = blockIdx.z, oB = blockIdx.y * TO, tB = blockIdx.x * TT;
    const int tid = threadIdx.x, tx = tid & 15, ty = tid >> 4;
    const float* xb = x + (size_t)b * Cin * Tin;

    unsigned long long acc2[8][4];
#pragma unroll
    for (int i = 0; i < 8; i++)
#pragma unroll
        for (int j = 0; j < 4; j++) acc2[i][j] = 0ULL;

    for (int i0 = 0; i0 < Cin; i0 += CK) {
        __syncthreads();
        const float* wp = w + (size_t)oB * Cin * K + (size_t)i0 * K;
        for (int idx = tid; idx < TO * CK * K; idx += 256) {
            int o = idx / (CK * K), rem = idx - o * (CK * K);
            sw[o][rem] = wp[(size_t)o * Cin * K + rem];
        }
        const int gb = tB * STRIDE - PAD;
        for (int idx = tid; idx < CK * SXL; idx += 256) {
            int ci = idx / SXL, p = idx - ci * SXL, gp = gb + p;
            float v = 0.f;
            if (gp >= 0 && gp < Tin) v = xb[(size_t)(i0 + ci) * Tin + gp];
            sx[ci][p] = v;
        }
        __syncthreads();
        for (int ci = 0; ci < CK; ci++) {
#pragma unroll
            for (int k = 0; k < K; k++) {
                float wv[8], xv[8];
#pragma unroll
                for (int ro = 0; ro < 8; ro++) wv[ro] = sw[ty + 16 * ro][ci * K + k];
#pragma unroll
                for (int ct = 0; ct < 8; ct++) xv[ct] = sx[ci][(tx + 16 * ct) * STRIDE + k];
                unsigned long long xp[4];
#pragma unroll
                for (int c = 0; c < 4; c++) xp[c] = pk2(xv[2 * c], xv[2 * c + 1]);
#pragma unroll
                for (int ro = 0; ro < 8; ro++) {
                    unsigned long long wd = pk2(wv[ro], wv[ro]);
#pragma unroll
                    for (int c = 0; c < 4; c++) acc2[ro][c] = fma2(wd, xp[c], acc2[ro][c]);
                }
            }
        }
    }
#pragma unroll
    for (int ro = 0; ro < 8; ro++) {
        int o = oB + ty + 16 * ro;
        float bv = bias[o];
#pragma unroll
        for (int c = 0; c < 4; c++) {
            float lo, hi;
            upk2(acc2[ro][c], lo, hi);
#pragma unroll
            for (int e = 0; e < 2; e++) {
                int t = tB + tx + 16 * (2 * c + e);
                float v = (e == 0 ? lo : hi) + bv;
                if (RELU) v = fmaxf(v, 0.f);
                y[((size_t)b * Cout + o) * Tout + t] = v;
            }
        }
    }
}

// ---------------- cnorm + argmin (proven) ----------------
__global__ __launch_bounds__(256) void cnorm_k(const float* __restrict__ cb)
{
    int j = blockIdx.x * 256 + threadIdx.x;
    float s = 0.f;
    for (int d = 0; d < CODE_D; d++) {
        float v = cb[(size_t)d * N_TOK + j];
        s = fmaf(v, v, s);
    }
    g_cn[j] = s;
}

__global__ __launch_bounds__(256)
void argmin_k(const float* __restrict__ cb, float* __restrict__ codes)
{
    constexpr int MR = 64, NC = 256, CK = 16;
    __shared__ __align__(16) unsigned long long sf2[CK][MR];
    __shared__ __align__(16) float sc[CK][NC];
    __shared__ float rbest[MR][33];
    __shared__ int ridx[MR][33];
    const int rBase = blockIdx.x * MR;
    const int tid = threadIdx.x, tx = tid & 31, ty = tid >> 5;

    float best[8];
    int bidx[8];
#pragma unroll
    for (int r = 0; r < 8; r++) { best[r] = 3.4e38f; bidx[r] = 24576; }

    for (int jt = 0; jt < N_TOK; jt += NC) {
        unsigned long long acc2[8][4];
#pragma unroll
        for (int i = 0; i < 8; i++)
#pragma unroll
            for (int j = 0; j < 4; j++) acc2[i][j] = 0ULL;
        for (int d0 = 0; d0 < CODE_D; d0 += CK) {
            __syncthreads();
#pragma unroll
            for (int j = 0; j < 4; j++) {
                int e = tid + 256 * j;
                int ci = e >> 6, r = e & 63;
                int row = rBase + r, b = row >> 9, t = row & 511;
                float v = g_lat[((size_t)b * CODE_D + (d0 + ci)) * T2 + t];
                sf2[ci][r] = pk2(v, v);
            }
#pragma unroll
            for (int j = 0; j < 16; j++) {
                int e = tid + 256 * j;
                sc[e >> 8][e & 255] = cb[(size_t)(d0 + (e >> 8)) * N_TOK + jt + (e & 255)];
            }
            __syncthreads();
#pragma unroll 4
            for (int ci = 0; ci < CK; ci++) {
                unsigned long long fd[8], cp[4];
#pragma unroll
                for (int rr = 0; rr < 8; rr++) fd[rr] = sf2[ci][ty * 8 + rr];
#pragma unroll
                for (int c = 0; c < 4; c++)
                    cp[c] = *(const unsigned long long*)(&sc[ci][2 * tx + 64 * c]);
#pragma unroll
                for (int rr = 0; rr < 8; rr++)
#pragma unroll
                    for (int c = 0; c < 4; c++) acc2[rr][c] = fma2(fd[rr], cp[c], acc2[rr][c]);
            }
        }
#pragma unroll
        for (int c = 0; c < 4; c++) {
            int j0 = jt + 2 * tx + 64 * c;
            float2 cn2 = *(const float2*)(&g_cn[j0]);
#pragma unroll
            for (int rr = 0; rr < 8; rr++) {
                float a0, a1;
                upk2(acc2[rr][c], a0, a1);
                float d0v = fmaf(-2.f, a0, cn2.x), d1v = fmaf(-2.f, a1, cn2.y);
                if (d0v < best[rr]) { best[rr] = d0v; bidx[rr] = j0; }
                if (d1v < best[rr]) { best[rr] = d1v; bidx[rr] = j0 + 1; }
            }
        }
    }
    __syncthreads();
#pragma unroll
    for (int rr = 0; rr < 8; rr++) {
        rbest[ty * 8 + rr][tx] = best[rr];
        ridx[ty * 8 + rr][tx] = bidx[rr];
    }
    __syncthreads();
    if (tid < MR) {
        float bv = rbest[tid][0];
        int bi = ridx[tid][0];
        for (int l = 1; l < 32; l++) {
            float v = rbest[tid][l];
            int ii = ridx[tid][l];
            if (v < bv || (v == bv && ii < bi)) { bv = v; bi = ii; }
        }
        codes[rBase + tid] = (float)bi;
    }
}

// ---------------- input mapping ----------------
static int find_sz(const int* s, int n, long long sz, int occ)
{
    int c = 0;
    for (int i = 0; i < n; i++)
        if ((long long)s[i] == sz) { if (c == occ) return i; c++; }
    return -1;
}
static bool map_inputs(const int* s, int n, long long mult, int* m)
{
    const long long esz[14] = {2621440LL, 122880LL, 512LL, 1572864LL, 1024LL,
                               9437184LL, 3072LL, 9437184LL, 3072LL,
                               3145728LL, 3072LL, 524288LL, 512LL, 4194304LL};
    const int occ[14] = {0,0,0,0,0, 0,0,1,1, 0,2, 0,1, 0};
    for (int r = 0; r < 14; r++) {
        m[r] = find_sz(s, n, esz[r] * mult, occ[r]);
        if (m[r] < 0) return false;
    }
    return true;
}

extern "C" void kernel_launch(void* const* d_in, const int* in_sizes, int n_in,
                              void* d_out, int out_size)
{
    int m[14];
    if (!map_inputs(in_sizes, n_in, 1, m))
        if (!map_inputs(in_sizes, n_in, 4, m))
            for (int r = 0; r < 14; r++) m[r] = r;

    const float* x   = (const float*)d_in[m[0]];
    const float* w1  = (const float*)d_in[m[1]];
    const float* b1  = (const float*)d_in[m[2]];
    const float* w2  = (const float*)d_in[m[3]];
    const float* b2  = (const float*)d_in[m[4]];
    const float* rwa = (const float*)d_in[m[5]];
    const float* rba = (const float*)d_in[m[6]];
    const float* rwb = (const float*)d_in[m[7]];
    const float* rbb = (const float*)d_in[m[8]];
    const float* rwc = (const float*)d_in[m[9]];
    const float* rbc = (const float*)d_in[m[10]];
    const float* wf  = (const float*)d_in[m[11]];
    const float* bf  = (const float*)d_in[m[12]];
    const float* cb  = (const float*)d_in[m[13]];
    float* codes = (float*)d_out;

    init_ptrs<<<1, 1>>>();

    for (int i = 0; i < N_RES; i++) {
        wsplit3h_k<<<4096, 256>>>(rwa + (size_t)i * HID2 * HID2 * 3, i);
        wsplit3h_k<<<4096, 256>>>(rwb + (size_t)i * HID2 * HID2 * 3, 3 + i);
        wsplit1h_k<<<4096, 256>>>(rwc + (size_t)i * HID2 * HID2, i);
    }
    wsplitfh_k<<<2048, 256>>>(wf);
    padzero_k<<<(3 * 2 * BATCH * 2 * 1024 + 255) / 256, 256>>>();

    conv_s2_k<3, 2, true><<<dim3(T1 / 128, HID1 / 128, BATCH), 256>>>(
        x, -1, BUF_H1, w1, b1, C_IN, T_IN, HID1, T1);
    conv_s2_k<3, 2, true><<<dim3(T2 / 128, HID2 / 128, BATCH), 256>>>(
        nullptr, BUF_H1, BUF_H2, w2, b2, HID1, T1, HID2, T2);

    xsplit_k<<<dim3(T2 / 32, HID2 / 32, BATCH), 256>>>();

    dim3 g3(T2 / 128, HID2 / 128, BATCH);
    const long long M20 = 1 << 20;
    for (int i = 0; i < N_RES; i++) {
        convmma_k<3, true, false, false, true><<<g3, 256>>>(
            VB_H2P, VB_W3P, (long long)i * 6 * M20, rba + (size_t)i * HID2,
            BUF_H2, VB_R1P, HID2);
        convmma_k<3, true, false, false, true><<<g3, 256>>>(
            VB_R1P, VB_W3P, (long long)(3 + i) * 6 * M20, rbb + (size_t)i * HID2,
            BUF_H2, VB_R2P, HID2);
        convmma_k<1, false, true, true, true><<<g3, 256>>>(
            VB_R2P, VB_W1P, (long long)i * 2 * M20, rbc + (size_t)i * HID2,
            BUF_H2, VB_H2P, HID2);
    }
    convmma_k<1, false, false, true, false>
        <<<dim3(T2 / 128, CODE_D / 128, BATCH), 256>>>(
        VB_H2P, VB_WFP, 0LL, bf, BUF_LAT, 0, CODE_D);

    cnorm_k<<<N_TOK / 256, 256>>>(cb);
    argmin_k<<<(BATCH * T2) / 64, 256>>>(cb, codes);
}